// round 11
// baseline (speedup 1.0000x reference)
#include <cuda_runtime.h>

#define B_   8
#define T_   2048
#define C_   192
#define TT   32
#define NBX  (T_ / TT)            // 64
#define RAD  10
#define NTAP (RAD + 1)
#define ROWS_X 58                 // TT + 26 : x(t0-13 .. t0+44)
#define ROWS_G 34                 // TT + 2  : rows t0-1 .. t0+32
#define NTH  384
#define SMEM_BYTES ((ROWS_X + ROWS_G) * C_ * 4)   // 70,656 B -> 3 CTAs/SM

// ---------------------------------------------------------------------------
// Fused tile body. EDGE=true adds boundary guards (blocks 0 and NBX-1 only).
// Thread = (channel c 0..191, row partition tr 0..1).
// x is staged in smem (coalesced, high MLP). u is NEVER materialized: the
// heat conv computes u on the fly via a sliding h-chain into a 21-reg ring.
// ---------------------------------------------------------------------------
template<bool EDGE>
__device__ __forceinline__ void run_tile(
    const float* __restrict__ xb,
    const float* __restrict__ dw, const float* __restrict__ db,
    const float* __restrict__ lw, const float* __restrict__ lb,
    const float* __restrict__ gamma, const float* __restrict__ beta,
    const float* __restrict__ ow, const float* __restrict__ ob,
    const float* __restrict__ kk,
    float* __restrict__ outb,
    float* xs, float* vs, float* s_mu, float* s_rs, int t0)
{
    const int tid  = threadIdx.x;
    const int c    = tid % C_;
    const int tr   = tid / C_;     // 0 or 1
    const int lane = tid & 31, wid = tid >> 5;
    const int c2   = c >> 1;

    // ================= phase 1: stage x tile (coalesced) ====================
#pragma unroll
    for (int i = tr; i < ROWS_X; i += 2) {
        int t = t0 - 13 + i;
        float v;
        if (EDGE) v = (t >= 0 && t < T_) ? xb[(size_t)t*C_ + c] : 0.f;
        else      v = xb[(size_t)t*C_ + c];
        xs[i*C_ + c] = v;
    }
    __syncthreads();

    // ================= phase 2: fused u + heat conv -> vs ===================
    {
        const float dwu0 = dw[c2*3+0], dwu1 = dw[c2*3+1], dwu2 = dw[c2*3+2], dbu = db[c2];
        const float lwu0 = lw[c*3+0],  lwu1 = lw[c*3+1],  lwu2 = lw[c*3+2],  lbu = lb[c];

        // closed-form wrapped Gaussian taps: F(s) = exp(-s^2/(4k)) / (2*sqrt(pi*k))
        float f[NTAP];
        {
            const float kc = kk[c];
            const float amp = 0.5f * rsqrtf(3.14159265358979f * kc);
            const float inv = 0.25f / kc;
#pragma unroll
            for (int s = 0; s < NTAP; s++)
                f[s] = amp * expf(-(float)(s*s) * inv);
        }

        const int i0 = tr * 17;          // output rows [i0, i0+17)

        if (!EDGE) {
            // sliding h chain; u(tu) pushed into 21-reg ring.
            // tu starts at tbase-10 where tbase = t0-1+i0 (time of first output row).
            // x(tau) lives at xs row (tau - t0 + 13); first h needs rows i0..i0+2.
            float xm = xs[(i0+0)*C_ + c2];
            float x0 = xs[(i0+1)*C_ + c2];
            float x1 = xs[(i0+2)*C_ + c2];
            float hm = dbu + dwu0*xm + dwu1*x0 + dwu2*x1;          // h(tbase-11)
            float x2 = xs[(i0+3)*C_ + c2];
            float hc = dbu + dwu0*x0 + dwu1*x1 + dwu2*x2;          // h(tbase-10)
            float xa = x1, xb2 = x2;

            float w[21];
            // warm-up: u(tbase-10 .. tbase+9) -> ring slots 0..19
#pragma unroll
            for (int q = 0; q < 20; q++) {
                float xn = xs[(i0+4+q)*C_ + c2];
                float hp = dbu + dwu0*xa + dwu1*xb2 + dwu2*xn;
                w[q] = lbu + lwu0*hm + lwu1*hc + lwu2*hp;
                hm = hc; hc = hp; xa = xb2; xb2 = xn;
            }
            // main: produce output row i0+j, consuming fresh u(tbase+10+j)
#pragma unroll
            for (int j = 0; j < 17; j++) {
                float xn = xs[(i0+24+j)*C_ + c2];
                float hp = dbu + dwu0*xa + dwu1*xb2 + dwu2*xn;
                w[(20+j) % 21] = lbu + lwu0*hm + lwu1*hc + lwu2*hp;
                hm = hc; hc = hp; xa = xb2; xb2 = xn;

                float v = f[0] * w[(j+10) % 21];
#pragma unroll
                for (int s = 1; s <= RAD; s++)
                    v += f[s] * (w[(j+10-s) % 21] + w[(j+10+s) % 21]);
                vs[(i0+j)*C_ + c] = v;
            }
        } else {
            // edge: recompute u per reflected tap (16/512 blocks only)
            auto u_at = [&](int t) -> float {
                const int r = t - t0 + 13;
                float a0 = xs[(r-2)*C_ + c2];
                float a1 = xs[(r-1)*C_ + c2];
                float a2 = xs[(r  )*C_ + c2];
                float a3 = xs[(r+1)*C_ + c2];
                float a4 = xs[(r+2)*C_ + c2];
                float h0 = (t-1 >= 0) ? (dbu + dwu0*a0 + dwu1*a1 + dwu2*a2) : 0.f;
                float h1 =              (dbu + dwu0*a1 + dwu1*a2 + dwu2*a3);
                float h2 = (t+1 < T_) ? (dbu + dwu0*a2 + dwu1*a3 + dwu2*a4) : 0.f;
                return lbu + lwu0*h0 + lwu1*h1 + lwu2*h2;
            };
#pragma unroll 1
            for (int j = 0; j < 17; j++) {
                const int i = i0 + j, t = t0 - 1 + i;
                int tc = t; tc = (tc >= 0) ? tc : (-1 - tc); tc = (tc < T_) ? tc : (2*T_ - 1 - tc);
                float v = f[0] * u_at(tc);
#pragma unroll 1
                for (int s = 1; s <= RAD; s++) {
                    int tl = t - s; tl = (tl >= 0) ? tl : (-1 - tl);
                    int th = t + s; th = (th < T_) ? th : (2*T_ - 1 - th);
                    v += f[s] * (u_at(tl) + u_at(th));
                }
                vs[i*C_ + c] = v;
            }
        }
    }
    __syncthreads();

    // ================= phase 3: LN stats (warp per row) =====================
    for (int r = wid; r < ROWS_G; r += 12) {
        float s1 = 0.f, s2 = 0.f;
#pragma unroll
        for (int q = 0; q < 6; q++) {
            float v = vs[r*C_ + lane + 32*q];
            s1 += v; s2 += v*v;
        }
#pragma unroll
        for (int m = 16; m; m >>= 1) {
            s1 += __shfl_xor_sync(0xffffffffu, s1, m);
            s2 += __shfl_xor_sync(0xffffffffu, s2, m);
        }
        if (lane == 0) {
            float mu  = s1 * (1.0f/C_);
            float var = s2 * (1.0f/C_) - mu*mu;
            s_mu[r] = mu;
            s_rs[r] = rsqrtf(var + 1e-5f);
        }
    }
    __syncthreads();

    // ================= phase 4: gate (LN apply + silu(z)), z from xs ========
    {
        const int zc2 = 96 + c2;
        const float dwz0 = dw[zc2*3+0], dwz1 = dw[zc2*3+1], dwz2 = dw[zc2*3+2], dbz = db[zc2];
        const float lwz0 = lw[(C_+c)*3+0], lwz1 = lw[(C_+c)*3+1], lwz2 = lw[(C_+c)*3+2], lbz = lb[C_+c];
        const float ga = gamma[c], be = beta[c];

        const int i0 = tr * 17;
        const int tstart = t0 - 1 + i0;
        // x(t) row = t - t0 + 13 = i + 12 for i = t - (t0-1)
        float x0 = xs[(i0+10)*C_ + zc2];
        float x1 = xs[(i0+11)*C_ + zc2];
        float x2 = xs[(i0+12)*C_ + zc2];
        float x3 = xs[(i0+13)*C_ + zc2];
        float hm = dbz + dwz0*x0 + dwz1*x1 + dwz2*x2;
        float hc = dbz + dwz0*x1 + dwz1*x2 + dwz2*x3;
        if (EDGE) {
            if (tstart-1 < 0 || tstart-1 >= T_) hm = 0.f;
            if (tstart   < 0 || tstart   >= T_) hc = 0.f;
        }
        float xa = x2, xb2 = x3;
#pragma unroll
        for (int j = 0; j < 17; j++) {
            const int i = i0 + j, t = tstart + j;
            float xn = xs[(i+14)*C_ + zc2];
            float hp = dbz + dwz0*xa + dwz1*xb2 + dwz2*xn;
            if (EDGE && (t+1 < 0 || t+1 >= T_)) hp = 0.f;
            float zv = lbz + lwz0*hm + lwz1*hc + lwz2*hp;
            hm = hc; hc = hp; xa = xb2; xb2 = xn;

            float v = vs[i*C_ + c];
            float g = (v - s_mu[i]) * s_rs[i] * ga + be;
            g *= zv * (1.0f / (1.0f + __expf(-zv)));
            if (EDGE && (t < 0 || t >= T_)) g = 0.f;
            vs[i*C_ + c] = g;
        }
    }
    __syncthreads();

    // ================= phase 5: final conv3 + store =========================
    {
        const float ow0 = ow[c*3+0], ow1 = ow[c*3+1], ow2 = ow[c*3+2], obc = ob[c];
        const int i0 = tr * 16;
        float g0 = vs[(i0+0)*C_ + c];
        float g1 = vs[(i0+1)*C_ + c];
#pragma unroll
        for (int j = 0; j < 16; j++) {
            float g2 = vs[(i0+j+2)*C_ + c];
            outb[(size_t)(t0 + i0 + j)*C_ + c] = obc + ow0*g0 + ow1*g1 + ow2*g2;
            g0 = g1; g1 = g2;
        }
    }
}

// ---------------------------------------------------------------------------
__global__ __launch_bounds__(NTH, 3)
void fused_kernel(const float* __restrict__ x,
                  const float* __restrict__ dw, const float* __restrict__ db,
                  const float* __restrict__ lw, const float* __restrict__ lb,
                  const float* __restrict__ gamma, const float* __restrict__ beta,
                  const float* __restrict__ ow, const float* __restrict__ ob,
                  const float* __restrict__ kk,
                  float* __restrict__ out)
{
    extern __shared__ float sm[];
    float* xs = sm;
    float* vs = sm + ROWS_X * C_;
    __shared__ float s_mu[ROWS_G], s_rs[ROWS_G];

    const int b  = blockIdx.y;
    const int bx = blockIdx.x;
    const int t0 = bx * TT;
    const float* xb   = x   + (size_t)b * T_ * C_;
    float*       outb = out + (size_t)b * T_ * C_;

    if (bx == 0 || bx == NBX - 1)
        run_tile<true >(xb, dw, db, lw, lb, gamma, beta, ow, ob, kk, outb,
                        xs, vs, s_mu, s_rs, t0);
    else
        run_tile<false>(xb, dw, db, lw, lb, gamma, beta, ow, ob, kk, outb,
                        xs, vs, s_mu, s_rs, t0);
}

// ---------------------------------------------------------------------------
extern "C" void kernel_launch(void* const* d_in, const int* in_sizes, int n_in,
                              void* d_out, int out_size)
{
    const float* x  = (const float*)d_in[0];
    const float* dw = (const float*)d_in[1];
    const float* db = (const float*)d_in[2];
    const float* lw = (const float*)d_in[3];
    const float* lb = (const float*)d_in[4];
    const float* ga = (const float*)d_in[5];
    const float* be = (const float*)d_in[6];
    const float* ow = (const float*)d_in[7];
    const float* ob = (const float*)d_in[8];
    const float* k  = (const float*)d_in[9];
    float* out = (float*)d_out;

    cudaFuncSetAttribute(fused_kernel, cudaFuncAttributeMaxDynamicSharedMemorySize,
                         SMEM_BYTES);

    fused_kernel<<<dim3(NBX, B_), NTH, SMEM_BYTES>>>(x, dw, db, lw, lb,
                                                     ga, be, ow, ob, k, out);
}

// round 13
// speedup vs baseline: 1.2986x; 1.2986x over previous
#include <cuda_runtime.h>

#define B_   8
#define T_   2048
#define C_   192
#define TT   64
#define NBX  (T_ / TT)            // 32
#define RAD  8
#define NTAP (RAD + 1)
#define RING 17                   // 2*RAD+1
#define ROWS_XU 86                // x(t0-11 .. t0+74), channels 0..95
#define ROWS_XZ 70                // x(t0-3  .. t0+66), channels 96..191
#define ROWS_G  66                // v rows t0-1 .. t0+64
#define NTH  384
#define SMEM_BYTES ((ROWS_XU + ROWS_XZ) * 96 * 4 + ROWS_G * C_ * 4)  // 110,592 B

// ---------------------------------------------------------------------------
// Fused tile. EDGE=true only for blocks 0 and NBX-1.
// Thread = (channel c 0..191, row partition tr 0..1; 33 rows each).
// x staged in two half-channel buffers; u never materialized (h-chain + ring).
// ---------------------------------------------------------------------------
template<bool EDGE>
__device__ __forceinline__ void run_tile(
    const float* __restrict__ xb,
    const float* __restrict__ dw, const float* __restrict__ db,
    const float* __restrict__ lw, const float* __restrict__ lb,
    const float* __restrict__ gamma, const float* __restrict__ beta,
    const float* __restrict__ ow, const float* __restrict__ ob,
    const float* __restrict__ kk,
    float* __restrict__ outb,
    float* xu, float* xz, float* vs, float* s_mu, float* s_rs, int t0)
{
    const int tid  = threadIdx.x;
    const int c    = tid % C_;
    const int tr   = tid / C_;     // 0 or 1
    const int lane = tid & 31, wid = tid >> 5;
    const int c2   = c >> 1;

    // ================= phase 1: stage x halves (coalesced) ==================
    for (int idx = tid; idx < ROWS_XU * 96; idx += NTH) {
        const int r = idx / 96, ch = idx % 96;
        const int t = t0 - 11 + r;
        float v;
        if (EDGE) v = (t >= 0 && t < T_) ? xb[(size_t)t*C_ + ch] : 0.f;
        else      v = xb[(size_t)t*C_ + ch];
        xu[idx] = v;
    }
    for (int idx = tid; idx < ROWS_XZ * 96; idx += NTH) {
        const int r = idx / 96, ch = idx % 96;
        const int t = t0 - 3 + r;
        float v;
        if (EDGE) v = (t >= 0 && t < T_) ? xb[(size_t)t*C_ + 96 + ch] : 0.f;
        else      v = xb[(size_t)t*C_ + 96 + ch];
        xz[idx] = v;
    }
    __syncthreads();

    // ================= phase 2: fused u + heat conv -> vs ===================
    {
        const float dwu0 = dw[c2*3+0], dwu1 = dw[c2*3+1], dwu2 = dw[c2*3+2], dbu = db[c2];
        const float lwu0 = lw[c*3+0],  lwu1 = lw[c*3+1],  lwu2 = lw[c*3+2],  lbu = lb[c];

        // closed-form wrapped Gaussian taps: F(s) = exp(-s^2/(4k)) / (2*sqrt(pi*k))
        float f[NTAP];
        {
            const float kc = kk[c];
            const float amp = 0.5f * rsqrtf(3.14159265358979f * kc);
            const float inv = 0.25f / kc;
#pragma unroll
            for (int s = 0; s < NTAP; s++)
                f[s] = amp * expf(-(float)(s*s) * inv);
        }

        const int i0 = tr * 33;          // output rows [i0, i0+33)

        if (!EDGE) {
            // x(t) lives at xu row (t - t0 + 11); first output time tbase = t0-1+i0.
            float xm = xu[(i0+0)*96 + c2];
            float x0 = xu[(i0+1)*96 + c2];
            float x1 = xu[(i0+2)*96 + c2];
            float x2 = xu[(i0+3)*96 + c2];
            float hm = dbu + dwu0*xm + dwu1*x0 + dwu2*x1;   // h(tbase-9)
            float hc = dbu + dwu0*x0 + dwu1*x1 + dwu2*x2;   // h(tbase-8)
            float xa = x1, xb2 = x2;

            float w[RING];
            // warm-up: u(tbase-8 .. tbase+7) -> slots 0..15
#pragma unroll
            for (int q = 0; q < RING - 1; q++) {
                float xn = xu[(i0+4+q)*96 + c2];
                float hp = dbu + dwu0*xa + dwu1*xb2 + dwu2*xn;
                w[q] = lbu + lwu0*hm + lwu1*hc + lwu2*hp;
                hm = hc; hc = hp; xa = xb2; xb2 = xn;
            }
            // main: output row i0+j; fresh u(tbase+8+j) in slot (16+j)%17
#pragma unroll
            for (int j = 0; j < 33; j++) {
                float xn = xu[(i0+20+j)*96 + c2];
                float hp = dbu + dwu0*xa + dwu1*xb2 + dwu2*xn;
                w[(RING-1+j) % RING] = lbu + lwu0*hm + lwu1*hc + lwu2*hp;
                hm = hc; hc = hp; xa = xb2; xb2 = xn;

                float v = f[0] * w[(j+RAD) % RING];
#pragma unroll
                for (int s = 1; s <= RAD; s++)
                    v += f[s] * (w[(j+RAD-s) % RING] + w[(j+RAD+s) % RING]);
                vs[(i0+j)*C_ + c] = v;
            }
        } else {
            // edge blocks: recompute u per reflected tap
            auto u_at = [&](int t) -> float {
                const int r = t - t0 + 11;
                float a0 = xu[(r-2)*96 + c2];
                float a1 = xu[(r-1)*96 + c2];
                float a2 = xu[(r  )*96 + c2];
                float a3 = xu[(r+1)*96 + c2];
                float a4 = xu[(r+2)*96 + c2];
                float h0 = (t-1 >= 0) ? (dbu + dwu0*a0 + dwu1*a1 + dwu2*a2) : 0.f;
                float h1 =              (dbu + dwu0*a1 + dwu1*a2 + dwu2*a3);
                float h2 = (t+1 < T_) ? (dbu + dwu0*a2 + dwu1*a3 + dwu2*a4) : 0.f;
                return lbu + lwu0*h0 + lwu1*h1 + lwu2*h2;
            };
#pragma unroll 1
            for (int j = 0; j < 33; j++) {
                const int i = i0 + j, t = t0 - 1 + i;
                int tc = t; tc = (tc >= 0) ? tc : (-1 - tc); tc = (tc < T_) ? tc : (2*T_ - 1 - tc);
                float v = f[0] * u_at(tc);
#pragma unroll 1
                for (int s = 1; s <= RAD; s++) {
                    int tl = t - s; tl = (tl >= 0) ? tl : (-1 - tl);
                    int th = t + s; th = (th < T_) ? th : (2*T_ - 1 - th);
                    v += f[s] * (u_at(tl) + u_at(th));
                }
                vs[i*C_ + c] = v;
            }
        }
    }
    __syncthreads();

    // ================= phase 3: LN stats (warp per row) =====================
    for (int r = wid; r < ROWS_G; r += 12) {
        float s1 = 0.f, s2 = 0.f;
#pragma unroll
        for (int q = 0; q < 6; q++) {
            float v = vs[r*C_ + lane + 32*q];
            s1 += v; s2 += v*v;
        }
#pragma unroll
        for (int m = 16; m; m >>= 1) {
            s1 += __shfl_xor_sync(0xffffffffu, s1, m);
            s2 += __shfl_xor_sync(0xffffffffu, s2, m);
        }
        if (lane == 0) {
            float mu  = s1 * (1.0f/C_);
            float var = s2 * (1.0f/C_) - mu*mu;
            s_mu[r] = mu;
            s_rs[r] = rsqrtf(var + 1e-5f);
        }
    }
    __syncthreads();

    // ================= phase 4: gate (LN apply + silu(z)) ===================
    {
        const int zc2 = 96 + c2;
        const float dwz0 = dw[zc2*3+0], dwz1 = dw[zc2*3+1], dwz2 = dw[zc2*3+2], dbz = db[zc2];
        const float lwz0 = lw[(C_+c)*3+0], lwz1 = lw[(C_+c)*3+1], lwz2 = lw[(C_+c)*3+2], lbz = lb[C_+c];
        const float ga = gamma[c], be = beta[c];

        const int i0 = tr * 33;
        const int tstart = t0 - 1 + i0;
        // x(t) lives at xz row (t - t0 + 3): row of x(tstart-2) = i0.
        float x0 = xz[(i0+0)*96 + c2];
        float x1 = xz[(i0+1)*96 + c2];
        float x2 = xz[(i0+2)*96 + c2];
        float x3 = xz[(i0+3)*96 + c2];
        float hm = dbz + dwz0*x0 + dwz1*x1 + dwz2*x2;
        float hc = dbz + dwz0*x1 + dwz1*x2 + dwz2*x3;
        if (EDGE) {
            if (tstart-1 < 0 || tstart-1 >= T_) hm = 0.f;
            if (tstart   < 0 || tstart   >= T_) hc = 0.f;
        }
        float xa = x2, xb2 = x3;
#pragma unroll
        for (int j = 0; j < 33; j++) {
            const int i = i0 + j, t = tstart + j;
            float xn = xz[(i+4)*96 + c2];
            float hp = dbz + dwz0*xa + dwz1*xb2 + dwz2*xn;
            if (EDGE && (t+1 < 0 || t+1 >= T_)) hp = 0.f;
            float zv = lbz + lwz0*hm + lwz1*hc + lwz2*hp;
            hm = hc; hc = hp; xa = xb2; xb2 = xn;

            float v = vs[i*C_ + c];
            float g = (v - s_mu[i]) * s_rs[i] * ga + be;
            g *= zv * (1.0f / (1.0f + __expf(-zv)));
            if (EDGE && (t < 0 || t >= T_)) g = 0.f;
            vs[i*C_ + c] = g;
        }
    }
    __syncthreads();

    // ================= phase 5: final conv3 + store =========================
    {
        const float ow0 = ow[c*3+0], ow1 = ow[c*3+1], ow2 = ow[c*3+2], obc = ob[c];
        const int i0 = tr * 32;
        float g0 = vs[(i0+0)*C_ + c];
        float g1 = vs[(i0+1)*C_ + c];
#pragma unroll
        for (int j = 0; j < 32; j++) {
            float g2 = vs[(i0+j+2)*C_ + c];
            outb[(size_t)(t0 + i0 + j)*C_ + c] = obc + ow0*g0 + ow1*g1 + ow2*g2;
            g0 = g1; g1 = g2;
        }
    }
}

// ---------------------------------------------------------------------------
__global__ __launch_bounds__(NTH, 2)
void fused_kernel(const float* __restrict__ x,
                  const float* __restrict__ dw, const float* __restrict__ db,
                  const float* __restrict__ lw, const float* __restrict__ lb,
                  const float* __restrict__ gamma, const float* __restrict__ beta,
                  const float* __restrict__ ow, const float* __restrict__ ob,
                  const float* __restrict__ kk,
                  float* __restrict__ out)
{
    extern __shared__ float sm[];
    float* xu = sm;
    float* xz = sm + ROWS_XU * 96;
    float* vs = sm + (ROWS_XU + ROWS_XZ) * 96;
    __shared__ float s_mu[ROWS_G], s_rs[ROWS_G];

    const int b  = blockIdx.y;
    const int bx = blockIdx.x;
    const int t0 = bx * TT;
    const float* xb   = x   + (size_t)b * T_ * C_;
    float*       outb = out + (size_t)b * T_ * C_;

    if (bx == 0 || bx == NBX - 1)
        run_tile<true >(xb, dw, db, lw, lb, gamma, beta, ow, ob, kk, outb,
                        xu, xz, vs, s_mu, s_rs, t0);
    else
        run_tile<false>(xb, dw, db, lw, lb, gamma, beta, ow, ob, kk, outb,
                        xu, xz, vs, s_mu, s_rs, t0);
}

// ---------------------------------------------------------------------------
extern "C" void kernel_launch(void* const* d_in, const int* in_sizes, int n_in,
                              void* d_out, int out_size)
{
    const float* x  = (const float*)d_in[0];
    const float* dw = (const float*)d_in[1];
    const float* db = (const float*)d_in[2];
    const float* lw = (const float*)d_in[3];
    const float* lb = (const float*)d_in[4];
    const float* ga = (const float*)d_in[5];
    const float* be = (const float*)d_in[6];
    const float* ow = (const float*)d_in[7];
    const float* ob = (const float*)d_in[8];
    const float* k  = (const float*)d_in[9];
    float* out = (float*)d_out;

    cudaFuncSetAttribute(fused_kernel, cudaFuncAttributeMaxDynamicSharedMemorySize,
                         SMEM_BYTES);

    fused_kernel<<<dim3(NBX, B_), NTH, SMEM_BYTES>>>(x, dw, db, lw, lb,
                                                     ga, be, ow, ob, k, out);
}

// round 14
// speedup vs baseline: 2.9296x; 2.2559x over previous
#include <cuda_runtime.h>

#define B_   8
#define T_   2048
#define C_   192
#define TT   32
#define NBX  (T_ / TT)            // 64
#define RAD  8
#define NTAP (RAD + 1)
#define RING 17
#define ROWS_X 54                 // x(t0-11 .. t0+42)
#define ROWS_U 50                 // u(t0-9  .. t0+40)
#define ROWS_G 34                 // v(t0-1  .. t0+32)
#define NTH  384
#define SMEM_BYTES ((ROWS_X + ROWS_U + ROWS_G) * C_ * 4)   // 105,984 B

__device__ __forceinline__ int mirr(int t) {
    t = (t >= 0) ? t : (-1 - t);
    return (t < T_) ? t : (2 * T_ - 1 - t);
}

// ---------------------------------------------------------------------------
// Fused tile. EDGE=true only for blocks 0 and NBX-1.
// Skeleton = R7 champion (x,u,v staged in smem, TT=32, 2 CTAs/SM), with
// composite 5-tap convs (interior) and split-accumulator heat conv.
// ---------------------------------------------------------------------------
template<bool EDGE>
__device__ __forceinline__ void run_tile(
    const float* __restrict__ xb,
    const float* __restrict__ dw, const float* __restrict__ db,
    const float* __restrict__ lw, const float* __restrict__ lb,
    const float* __restrict__ gamma, const float* __restrict__ beta,
    const float* __restrict__ ow, const float* __restrict__ ob,
    const float* __restrict__ kk,
    float* __restrict__ outb,
    float* xs, float* us, float* vs, float* s_mu, float* s_rs, int t0)
{
    const int tid  = threadIdx.x;
    const int c    = tid % C_;
    const int tr   = tid / C_;     // 0 or 1
    const int lane = tid & 31, wid = tid >> 5;
    const int c2   = c >> 1;

    // ================= phase 1: stage x tile (coalesced) ====================
#pragma unroll
    for (int i = tr; i < ROWS_X; i += 2) {
        int t = t0 - 11 + i;
        float v;
        if (EDGE) v = (t >= 0 && t < T_) ? xb[(size_t)t*C_ + c] : 0.f;
        else      v = xb[(size_t)t*C_ + c];
        xs[i*C_ + c] = v;
    }
    __syncthreads();

    // ================= phase 2: u build =====================================
    {
        const float dwu0 = dw[c2*3+0], dwu1 = dw[c2*3+1], dwu2 = dw[c2*3+2], dbu = db[c2];
        const float lwu0 = lw[c*3+0],  lwu1 = lw[c*3+1],  lwu2 = lw[c*3+2],  lbu = lb[c];

        if (!EDGE) {
            // composite 5-tap: u(t) = gb + sum_d g[d]*x(t-2+d)
            const float g0 = lwu0*dwu0;
            const float g1 = lwu0*dwu1 + lwu1*dwu0;
            const float g2 = lwu0*dwu2 + lwu1*dwu1 + lwu2*dwu0;
            const float g3 = lwu1*dwu2 + lwu2*dwu1;
            const float g4 = lwu2*dwu2;
            const float gb = lbu + dbu*(lwu0 + lwu1 + lwu2);

            const int i0 = tr * 25;    // u rows [i0, i0+25)
            float a0 = xs[(i0+0)*C_ + c2];
            float a1 = xs[(i0+1)*C_ + c2];
            float a2 = xs[(i0+2)*C_ + c2];
            float a3 = xs[(i0+3)*C_ + c2];
#pragma unroll
            for (int j = 0; j < 25; j++) {
                float a4 = xs[(i0+j+4)*C_ + c2];
                float p  = gb + g0*a0 + g1*a1;         // chain depth 2
                float q  = g2*a2 + g3*a3 + g4*a4;      // chain depth ~2
                us[(i0+j)*C_ + c] = p + q;
                a0 = a1; a1 = a2; a2 = a3; a3 = a4;
            }
        } else {
            // guarded two-stage (cheap: reads xs)
#pragma unroll
            for (int i = tr; i < ROWS_U; i += 2) {
                const int t = t0 - 9 + i;     // xs row for t-2 is i
                float val = 0.f;
                if (t >= 0 && t < T_) {
                    float b0 = xs[(i+0)*C_ + c2];
                    float b1 = xs[(i+1)*C_ + c2];
                    float b2 = xs[(i+2)*C_ + c2];
                    float b3 = xs[(i+3)*C_ + c2];
                    float b4 = xs[(i+4)*C_ + c2];
                    float h0 = (t-1 >= 0) ? (dbu + dwu0*b0 + dwu1*b1 + dwu2*b2) : 0.f;
                    float h1 =              (dbu + dwu0*b1 + dwu1*b2 + dwu2*b3);
                    float h2 = (t+1 < T_) ? (dbu + dwu0*b2 + dwu1*b3 + dwu2*b4) : 0.f;
                    val = lbu + lwu0*h0 + lwu1*h1 + lwu2*h2;
                }
                us[i*C_ + c] = val;
            }
        }
    }
    __syncthreads();

    // ================= phase 3: heat conv -> vs =============================
    {
        // closed-form wrapped Gaussian taps: F(s) = exp(-s^2/(4k)) / (2*sqrt(pi*k))
        float f[NTAP];
        {
            const float kc = kk[c];
            const float amp = 0.5f * rsqrtf(3.14159265358979f * kc);
            const float inv = 0.25f / kc;
#pragma unroll
            for (int s = 0; s < NTAP; s++)
                f[s] = amp * expf(-(float)(s*s) * inv);
        }

        const int i0 = tr * 17;    // output rows [i0, i0+17)
        if (!EDGE) {
            // ring over us rows [i0 .. i0+32]; output row i0+j uses rows i0+j..i0+j+16
            float w[RING];
#pragma unroll
            for (int q = 0; q < RING - 1; q++) w[q] = us[(i0+q)*C_ + c];
#pragma unroll
            for (int j = 0; j < 17; j++) {
                w[(RING-1+j) % RING] = us[(i0+j+RING-1)*C_ + c];
                // center slot = (j+8)%17 ; taps s: slots (j+8±s)%17
                float acc0 = f[0]*w[(j+8) % RING]
                           + f[3]*(w[(j+5) % RING] + w[(j+11) % RING])
                           + f[6]*(w[(j+2) % RING] + w[(j+14) % RING]);
                float acc1 = f[1]*(w[(j+7) % RING] + w[(j+9)  % RING])
                           + f[4]*(w[(j+4) % RING] + w[(j+12) % RING])
                           + f[7]*(w[(j+1) % RING] + w[(j+15) % RING]);
                float acc2 = f[2]*(w[(j+6) % RING] + w[(j+10) % RING])
                           + f[5]*(w[(j+3) % RING] + w[(j+13) % RING])
                           + f[8]*(w[(j+0) % RING] + w[(j+16) % RING]);
                vs[(i0+j)*C_ + c] = (acc0 + acc1) + acc2;
            }
        } else {
            // guarded reflect reads from us (us row = tau - (t0-9))
            const int baseu = t0 - 9;
#pragma unroll
            for (int j = 0; j < 17; j++) {
                const int i = i0 + j, t = t0 - 1 + i;
                float v = f[0] * us[(mirr(t) - baseu)*C_ + c];
#pragma unroll
                for (int s = 1; s <= RAD; s++) {
                    int tl = mirr(t - s);
                    int th = mirr(t + s);
                    v += f[s] * (us[(tl - baseu)*C_ + c] + us[(th - baseu)*C_ + c]);
                }
                vs[i*C_ + c] = v;
            }
        }
    }
    __syncthreads();

    // ================= phase 4: LN stats (warp per row) =====================
    for (int r = wid; r < ROWS_G; r += 12) {
        float s1 = 0.f, s2 = 0.f;
#pragma unroll
        for (int q = 0; q < 6; q++) {
            float v = vs[r*C_ + lane + 32*q];
            s1 += v; s2 += v*v;
        }
#pragma unroll
        for (int m = 16; m; m >>= 1) {
            s1 += __shfl_xor_sync(0xffffffffu, s1, m);
            s2 += __shfl_xor_sync(0xffffffffu, s2, m);
        }
        if (lane == 0) {
            float mu  = s1 * (1.0f/C_);
            float var = s2 * (1.0f/C_) - mu*mu;
            s_mu[r] = mu;
            s_rs[r] = rsqrtf(var + 1e-5f);
        }
    }
    __syncthreads();

    // ================= phase 5: gate (LN apply + silu(z)) ===================
    {
        const int zc2 = 96 + c2;
        const float dwz0 = dw[zc2*3+0], dwz1 = dw[zc2*3+1], dwz2 = dw[zc2*3+2], dbz = db[zc2];
        const float lwz0 = lw[(C_+c)*3+0], lwz1 = lw[(C_+c)*3+1], lwz2 = lw[(C_+c)*3+2], lbz = lb[C_+c];
        const float ga = gamma[c], be = beta[c];

        const int i0 = tr * 17;
        if (!EDGE) {
            const float z0 = lwz0*dwz0;
            const float z1 = lwz0*dwz1 + lwz1*dwz0;
            const float z2 = lwz0*dwz2 + lwz1*dwz1 + lwz2*dwz0;
            const float z3 = lwz1*dwz2 + lwz2*dwz1;
            const float z4 = lwz2*dwz2;
            const float zbias = lbz + dbz*(lwz0 + lwz1 + lwz2);

            // x(t-2) for row i (t=t0-1+i) is xs row i+8
            float a0 = xs[(i0+8 )*C_ + zc2];
            float a1 = xs[(i0+9 )*C_ + zc2];
            float a2 = xs[(i0+10)*C_ + zc2];
            float a3 = xs[(i0+11)*C_ + zc2];
#pragma unroll
            for (int j = 0; j < 17; j++) {
                const int i = i0 + j;
                float a4 = xs[(i+12)*C_ + zc2];
                float p  = zbias + z0*a0 + z1*a1;
                float q  = z2*a2 + z3*a3 + z4*a4;
                float zv = p + q;
                a0 = a1; a1 = a2; a2 = a3; a3 = a4;

                float v = vs[i*C_ + c];
                float g = (v - s_mu[i]) * s_rs[i] * ga + be;
                g *= zv * (1.0f / (1.0f + __expf(-zv)));
                vs[i*C_ + c] = g;
            }
        } else {
#pragma unroll
            for (int j = 0; j < 17; j++) {
                const int i = i0 + j, t = t0 - 1 + i;
                float b0 = xs[(i+8 )*C_ + zc2];
                float b1 = xs[(i+9 )*C_ + zc2];
                float b2 = xs[(i+10)*C_ + zc2];
                float b3 = xs[(i+11)*C_ + zc2];
                float b4 = xs[(i+12)*C_ + zc2];
                float h0 = (t-1 >= 0) ? (dbz + dwz0*b0 + dwz1*b1 + dwz2*b2) : 0.f;
                float h1 =              (dbz + dwz0*b1 + dwz1*b2 + dwz2*b3);
                float h2 = (t+1 < T_) ? (dbz + dwz0*b2 + dwz1*b3 + dwz2*b4) : 0.f;
                float zv = lbz + lwz0*h0 + lwz1*h1 + lwz2*h2;

                float v = vs[i*C_ + c];
                float g = (v - s_mu[i]) * s_rs[i] * ga + be;
                g *= zv * (1.0f / (1.0f + __expf(-zv)));
                if (t < 0 || t >= T_) g = 0.f;
                vs[i*C_ + c] = g;
            }
        }
    }
    __syncthreads();

    // ================= phase 6: final conv3 + store =========================
    {
        const float ow0 = ow[c*3+0], ow1 = ow[c*3+1], ow2 = ow[c*3+2], obc = ob[c];
        const int i0 = tr * 16;
        float g0 = vs[(i0+0)*C_ + c];
        float g1 = vs[(i0+1)*C_ + c];
#pragma unroll
        for (int j = 0; j < 16; j++) {
            float g2 = vs[(i0+j+2)*C_ + c];
            outb[(size_t)(t0 + i0 + j)*C_ + c] = obc + ow0*g0 + ow1*g1 + ow2*g2;
            g0 = g1; g1 = g2;
        }
    }
}

// ---------------------------------------------------------------------------
__global__ __launch_bounds__(NTH, 2)
void fused_kernel(const float* __restrict__ x,
                  const float* __restrict__ dw, const float* __restrict__ db,
                  const float* __restrict__ lw, const float* __restrict__ lb,
                  const float* __restrict__ gamma, const float* __restrict__ beta,
                  const float* __restrict__ ow, const float* __restrict__ ob,
                  const float* __restrict__ kk,
                  float* __restrict__ out)
{
    extern __shared__ float sm[];
    float* xs = sm;
    float* us = sm + ROWS_X * C_;
    float* vs = sm + (ROWS_X + ROWS_U) * C_;
    __shared__ float s_mu[ROWS_G], s_rs[ROWS_G];

    const int b  = blockIdx.y;
    const int bx = blockIdx.x;
    const int t0 = bx * TT;
    const float* xb   = x   + (size_t)b * T_ * C_;
    float*       outb = out + (size_t)b * T_ * C_;

    if (bx == 0 || bx == NBX - 1)
        run_tile<true >(xb, dw, db, lw, lb, gamma, beta, ow, ob, kk, outb,
                        xs, us, vs, s_mu, s_rs, t0);
    else
        run_tile<false>(xb, dw, db, lw, lb, gamma, beta, ow, ob, kk, outb,
                        xs, us, vs, s_mu, s_rs, t0);
}

// ---------------------------------------------------------------------------
extern "C" void kernel_launch(void* const* d_in, const int* in_sizes, int n_in,
                              void* d_out, int out_size)
{
    const float* x  = (const float*)d_in[0];
    const float* dw = (const float*)d_in[1];
    const float* db = (const float*)d_in[2];
    const float* lw = (const float*)d_in[3];
    const float* lb = (const float*)d_in[4];
    const float* ga = (const float*)d_in[5];
    const float* be = (const float*)d_in[6];
    const float* ow = (const float*)d_in[7];
    const float* ob = (const float*)d_in[8];
    const float* k  = (const float*)d_in[9];
    float* out = (float*)d_out;

    cudaFuncSetAttribute(fused_kernel, cudaFuncAttributeMaxDynamicSharedMemorySize,
                         SMEM_BYTES);

    fused_kernel<<<dim3(NBX, B_), NTH, SMEM_BYTES>>>(x, dw, db, lw, lb,
                                                     ga, be, ow, ob, k, out);
}

// round 15
// speedup vs baseline: 3.2713x; 1.1166x over previous
#include <cuda_runtime.h>

#define B_   8
#define T_   2048
#define C_   192
#define TT   128
#define NBX  (T_ / TT)            // 16
#define RAD  8
#define NTAP (RAD + 1)
#define RING 17
#define ROWS_U 146                // u(t0-9 .. t0+136)
#define ROWS_G 130                // v(t0-1 .. t0+128)
#define NTH  768
#define SMEM_BYTES ((ROWS_U + ROWS_G) * C_ * 4)   // 211,968 B -> 1 CTA/SM, 1 wave

// ---------------------------------------------------------------------------
// Fused tile, TT=128, one CTA per SM, single wave (128 blocks).
// Thread = (channel c 0..191, partition tr 0..3). x streamed from global in
// batched 12-wide chunks (explicit MLP); u and v staged in smem.
// EDGE blocks (bx 0, NBX-1) use guarded u/gate + ring-with-mirror-corrections.
// ---------------------------------------------------------------------------
template<bool EDGE>
__device__ __forceinline__ void run_tile(
    const float* __restrict__ xb,
    const float* __restrict__ dw, const float* __restrict__ db,
    const float* __restrict__ lw, const float* __restrict__ lb,
    const float* __restrict__ gamma, const float* __restrict__ beta,
    const float* __restrict__ ow, const float* __restrict__ ob,
    const float* __restrict__ kk,
    float* __restrict__ outb,
    float* us, float* vs, float* s_mu, float* s_rs, int t0)
{
    const int tid  = threadIdx.x;
    const int c    = tid % C_;
    const int tr   = tid / C_;     // 0..3
    const int lane = tid & 31, wid = tid >> 5;
    const int c2   = c >> 1;

    // ================= phase A: u build (x streamed, chunked loads) =========
    {
        const float dwu0 = dw[c2*3+0], dwu1 = dw[c2*3+1], dwu2 = dw[c2*3+2], dbu = db[c2];
        const float lwu0 = lw[c*3+0],  lwu1 = lw[c*3+1],  lwu2 = lw[c*3+2],  lbu = lb[c];
        const float* xc = xb + c2;

        const int i0a = tr * 37;
        const int cnt = (tr < 3) ? 37 : 35;

        if (!EDGE) {
            const float g0 = lwu0*dwu0;
            const float g1 = lwu0*dwu1 + lwu1*dwu0;
            const float g2 = lwu0*dwu2 + lwu1*dwu1 + lwu2*dwu0;
            const float g3 = lwu1*dwu2 + lwu2*dwu1;
            const float g4 = lwu2*dwu2;
            const float gb = lbu + dbu*(lwu0 + lwu1 + lwu2);
#pragma unroll
            for (int q = 0; q < 5; q++) {
                const int tfirst = t0 - 9 + i0a + 8*q;   // time of first row in chunk
                float xv[12];
#pragma unroll
                for (int d = 0; d < 12; d++)
                    xv[d] = xc[(size_t)(tfirst - 2 + d) * C_];
#pragma unroll
                for (int j = 0; j < 8; j++) {
                    const int row = i0a + 8*q + j;
                    if (8*q + j < cnt) {
                        float p = gb + g0*xv[j] + g1*xv[j+1];
                        float r = g2*xv[j+2] + g3*xv[j+3] + g4*xv[j+4];
                        us[row*C_ + c] = p + r;
                    }
                }
            }
        } else {
#pragma unroll
            for (int q = 0; q < 5; q++) {
                const int tfirst = t0 - 9 + i0a + 8*q;
                float xv[12];
#pragma unroll
                for (int d = 0; d < 12; d++) {
                    const int tt = tfirst - 2 + d;
                    xv[d] = (tt >= 0 && tt < T_) ? xc[(size_t)tt * C_] : 0.f;
                }
#pragma unroll
                for (int j = 0; j < 8; j++) {
                    const int row = i0a + 8*q + j;
                    if (8*q + j < cnt) {
                        const int t = tfirst + j;
                        float h0 = dbu + dwu0*xv[j]   + dwu1*xv[j+1] + dwu2*xv[j+2];
                        float h1 = dbu + dwu0*xv[j+1] + dwu1*xv[j+2] + dwu2*xv[j+3];
                        float h2 = dbu + dwu0*xv[j+2] + dwu1*xv[j+3] + dwu2*xv[j+4];
                        if (t - 1 < 0)   h0 = 0.f;
                        if (t + 1 >= T_) h2 = 0.f;
                        float uv = lbu + lwu0*h0 + lwu1*h1 + lwu2*h2;
                        if (t < 0 || t >= T_) uv = 0.f;
                        us[row*C_ + c] = uv;
                    }
                }
            }
        }
    }
    __syncthreads();

    // ================= phase B: heat conv (ring) -> vs ======================
    {
        float f[NTAP];
        {
            const float kc = kk[c];
            const float amp = 0.5f * rsqrtf(3.14159265358979f * kc);
            const float inv = 0.25f / kc;
#pragma unroll
            for (int s = 0; s < NTAP; s++)
                f[s] = amp * expf(-(float)(s*s) * inv);
        }

        const int i0 = tr * 33;
        const int cnt = (tr < 3) ? 33 : 31;

        float w[RING];
#pragma unroll
        for (int q = 0; q < RING - 1; q++) w[q] = us[(i0+q)*C_ + c];
#pragma unroll
        for (int j = 0; j < 33; j++) {
            if (j < cnt) {
                w[(RING-1+j) % RING] = us[(i0+j+RING-1)*C_ + c];
                float acc0 = f[0]*w[(j+8) % RING]
                           + f[3]*(w[(j+5) % RING] + w[(j+11) % RING])
                           + f[6]*(w[(j+2) % RING] + w[(j+14) % RING]);
                float acc1 = f[1]*(w[(j+7) % RING] + w[(j+9)  % RING])
                           + f[4]*(w[(j+4) % RING] + w[(j+12) % RING])
                           + f[7]*(w[(j+1) % RING] + w[(j+15) % RING]);
                float acc2 = f[2]*(w[(j+6) % RING] + w[(j+10) % RING])
                           + f[5]*(w[(j+3) % RING] + w[(j+13) % RING])
                           + f[8]*(w[(j+0) % RING] + w[(j+16) % RING]);
                vs[(i0+j)*C_ + c] = (acc0 + acc1) + acc2;
            }
        }

        if (EDGE) {
            // mirror corrections (u outside [0,T) is zero-padded, so just add
            // the reflected contributions)
            if (t0 == 0 && tr == 0) {
                // rows i=1..8 (t = 0..7): add sum_{s=t+1}^{8} f[s]*u(s-t-1)
#pragma unroll 1
                for (int i = 1; i <= 8; i++) {
                    const int t = i - 1;
                    float acc = 0.f;
#pragma unroll 1
                    for (int s = t + 1; s <= 8; s++)
                        acc += f[s] * us[(s - t + 8)*C_ + c];   // row = (s-t-1)+9
                    vs[i*C_ + c] += acc;
                }
            }
            if (t0 == T_ - TT && tr == 3) {
                // rows i=121..128 (t = 2040..2047): add sum_{s>=2048-t} f[s]*u(4095-t-s)
#pragma unroll 1
                for (int i = 121; i <= 128; i++) {
                    const int t = t0 - 1 + i;
                    float acc = 0.f;
#pragma unroll 1
                    for (int s = T_ - t; s <= 8; s++)
                        acc += f[s] * us[(4095 - t - s - t0 + 9)*C_ + c];
                    vs[i*C_ + c] += acc;
                }
            }
        }
    }
    __syncthreads();

    // ================= phase C: LN stats (warp per row) =====================
    for (int r = wid; r < ROWS_G; r += 24) {
        float s1 = 0.f, s2 = 0.f;
#pragma unroll
        for (int q = 0; q < 6; q++) {
            float v = vs[r*C_ + lane + 32*q];
            s1 += v; s2 += v*v;
        }
#pragma unroll
        for (int m = 16; m; m >>= 1) {
            s1 += __shfl_xor_sync(0xffffffffu, s1, m);
            s2 += __shfl_xor_sync(0xffffffffu, s2, m);
        }
        if (lane == 0) {
            float mu  = s1 * (1.0f/C_);
            float var = s2 * (1.0f/C_) - mu*mu;
            s_mu[r] = mu;
            s_rs[r] = rsqrtf(var + 1e-5f);
        }
    }
    __syncthreads();

    // ================= phase D: gate (LN apply + silu(z)), z streamed =======
    {
        const int zch = 96 + c2;
        const float dwz0 = dw[zch*3+0], dwz1 = dw[zch*3+1], dwz2 = dw[zch*3+2], dbz = db[zch];
        const float lwz0 = lw[(C_+c)*3+0], lwz1 = lw[(C_+c)*3+1], lwz2 = lw[(C_+c)*3+2], lbz = lb[C_+c];
        const float ga = gamma[c], be = beta[c];
        const float* xz = xb + zch;

        const int i0 = tr * 33;
        const int cnt = (tr < 3) ? 33 : 31;

        if (!EDGE) {
            const float z0 = lwz0*dwz0;
            const float z1 = lwz0*dwz1 + lwz1*dwz0;
            const float z2 = lwz0*dwz2 + lwz1*dwz1 + lwz2*dwz0;
            const float z3 = lwz1*dwz2 + lwz2*dwz1;
            const float z4 = lwz2*dwz2;
            const float zbias = lbz + dbz*(lwz0 + lwz1 + lwz2);
#pragma unroll
            for (int q = 0; q < 5; q++) {
                const int tfirst = t0 - 1 + i0 + 8*q;
                float xv[12];
#pragma unroll
                for (int d = 0; d < 12; d++)
                    xv[d] = xz[(size_t)(tfirst - 2 + d) * C_];
#pragma unroll
                for (int j = 0; j < 8; j++) {
                    const int row = i0 + 8*q + j;
                    if (8*q + j < cnt) {
                        float p  = zbias + z0*xv[j] + z1*xv[j+1];
                        float r  = z2*xv[j+2] + z3*xv[j+3] + z4*xv[j+4];
                        float zv = p + r;
                        float v = vs[row*C_ + c];
                        float g = (v - s_mu[row]) * s_rs[row] * ga + be;
                        g *= zv * (1.0f / (1.0f + __expf(-zv)));
                        vs[row*C_ + c] = g;
                    }
                }
            }
        } else {
#pragma unroll
            for (int q = 0; q < 5; q++) {
                const int tfirst = t0 - 1 + i0 + 8*q;
                float xv[12];
#pragma unroll
                for (int d = 0; d < 12; d++) {
                    const int tt = tfirst - 2 + d;
                    xv[d] = (tt >= 0 && tt < T_) ? xz[(size_t)tt * C_] : 0.f;
                }
#pragma unroll
                for (int j = 0; j < 8; j++) {
                    const int row = i0 + 8*q + j;
                    if (8*q + j < cnt) {
                        const int t = tfirst + j;
                        float h0 = dbz + dwz0*xv[j]   + dwz1*xv[j+1] + dwz2*xv[j+2];
                        float h1 = dbz + dwz0*xv[j+1] + dwz1*xv[j+2] + dwz2*xv[j+3];
                        float h2 = dbz + dwz0*xv[j+2] + dwz1*xv[j+3] + dwz2*xv[j+4];
                        if (t - 1 < 0)   h0 = 0.f;
                        if (t + 1 >= T_) h2 = 0.f;
                        float zv = lbz + lwz0*h0 + lwz1*h1 + lwz2*h2;
                        float v = vs[row*C_ + c];
                        float g = (v - s_mu[row]) * s_rs[row] * ga + be;
                        g *= zv * (1.0f / (1.0f + __expf(-zv)));
                        if (t < 0 || t >= T_) g = 0.f;
                        vs[row*C_ + c] = g;
                    }
                }
            }
        }
    }
    __syncthreads();

    // ================= phase E: final conv3 + store =========================
    {
        const float ow0 = ow[c*3+0], ow1 = ow[c*3+1], ow2 = ow[c*3+2], obc = ob[c];
        const int i0e = tr * 32;
        float g0 = vs[(i0e+0)*C_ + c];
        float g1 = vs[(i0e+1)*C_ + c];
#pragma unroll
        for (int j = 0; j < 32; j++) {
            float g2 = vs[(i0e+j+2)*C_ + c];
            outb[(size_t)(t0 + i0e + j)*C_ + c] = obc + ow0*g0 + ow1*g1 + ow2*g2;
            g0 = g1; g1 = g2;
        }
    }
}

// ---------------------------------------------------------------------------
__global__ __launch_bounds__(NTH, 1)
void fused_kernel(const float* __restrict__ x,
                  const float* __restrict__ dw, const float* __restrict__ db,
                  const float* __restrict__ lw, const float* __restrict__ lb,
                  const float* __restrict__ gamma, const float* __restrict__ beta,
                  const float* __restrict__ ow, const float* __restrict__ ob,
                  const float* __restrict__ kk,
                  float* __restrict__ out)
{
    extern __shared__ float sm[];
    float* us = sm;
    float* vs = sm + ROWS_U * C_;
    __shared__ float s_mu[ROWS_G], s_rs[ROWS_G];

    const int b  = blockIdx.y;
    const int bx = blockIdx.x;
    const int t0 = bx * TT;
    const float* xb   = x   + (size_t)b * T_ * C_;
    float*       outb = out + (size_t)b * T_ * C_;

    if (bx == 0 || bx == NBX - 1)
        run_tile<true >(xb, dw, db, lw, lb, gamma, beta, ow, ob, kk, outb,
                        us, vs, s_mu, s_rs, t0);
    else
        run_tile<false>(xb, dw, db, lw, lb, gamma, beta, ow, ob, kk, outb,
                        us, vs, s_mu, s_rs, t0);
}

// ---------------------------------------------------------------------------
extern "C" void kernel_launch(void* const* d_in, const int* in_sizes, int n_in,
                              void* d_out, int out_size)
{
    const float* x  = (const float*)d_in[0];
    const float* dw = (const float*)d_in[1];
    const float* db = (const float*)d_in[2];
    const float* lw = (const float*)d_in[3];
    const float* lb = (const float*)d_in[4];
    const float* ga = (const float*)d_in[5];
    const float* be = (const float*)d_in[6];
    const float* ow = (const float*)d_in[7];
    const float* ob = (const float*)d_in[8];
    const float* k  = (const float*)d_in[9];
    float* out = (float*)d_out;

    cudaFuncSetAttribute(fused_kernel, cudaFuncAttributeMaxDynamicSharedMemorySize,
                         SMEM_BYTES);

    fused_kernel<<<dim3(NBX, B_), NTH, SMEM_BYTES>>>(x, dw, db, lw, lb,
                                                     ga, be, ow, ob, k, out);
}